// round 16
// baseline (speedup 1.0000x reference)
#include <cuda_runtime.h>
#include <cuda_fp16.h>
#include <math.h>
#include <stdint.h>

// ---------------- problem constants ----------------
#define BATCH   16
#define NFRAMES 8
#define SEQ     256
#define DMODEL  768
#define NHEADS  12
#define DHEAD   64
#define DFF     3072
#define ADC     128
#define ROWS    (BATCH*SEQ) // 4096
#define QKVN    2304

// ---------------- scratch (device globals; no allocations) ----------------
__device__ __align__(16) __half g_h16 [ROWS*DMODEL];
__device__ __align__(16) __half g_h1h [ROWS*ADC];
__device__ __align__(16) __half g_cv16[ROWS*ADC];
__device__ __align__(16) float  g_ad  [ROWS*DMODEL];
__device__ __align__(16) float  g_hs  [ROWS*DMODEL];
__device__ __align__(16) __half g_hn16[ROWS*DMODEL];
__device__ __align__(16) __half g_qkvh[ROWS*QKVN];
__device__ __align__(16) __half g_ctx16[ROWS*DMODEL];
__device__ __align__(16) float  g_hs2 [ROWS*DMODEL];
__device__ __align__(16) __half g_scoresh[BATCH*NHEADS*SEQ*SEQ]; // raw QK^T half
__device__ __align__(16) __half g_attnh [BATCH*NHEADS*SEQ*SEQ];  // probs half
__device__ __align__(16) __half g_ff16[ROWS*DFF];
__device__ int g_bucket[SEQ*SEQ];
// fp16 transposed weights [N][K]
__device__ __align__(16) __half g_wt_qkv[QKVN*DMODEL];
__device__ __align__(16) __half g_wt_o  [DMODEL*DMODEL];
__device__ __align__(16) __half g_wt_wi [DFF*DMODEL];
__device__ __align__(16) __half g_wt_wo [DMODEL*DFF];
__device__ __align__(16) __half g_wt_fc1[ADC*DMODEL];
__device__ __align__(16) __half g_wt_fc2[DMODEL*ADC];

// ================= helpers =================
__device__ __forceinline__ uint32_t smem_u32(const void* p) {
    uint32_t a;
    asm("{ .reg .u64 t; cvta.to.shared.u64 t, %1; cvt.u32.u64 %0, t; }" : "=r"(a) : "l"(p));
    return a;
}
__device__ __forceinline__ void cp16(uint32_t s, const void* g) {
    asm volatile("cp.async.cg.shared.global [%0], [%1], 16;" :: "r"(s), "l"(g));
}
#define CP_COMMIT() asm volatile("cp.async.commit_group;" ::: "memory")
#define CP_WAIT1()  asm volatile("cp.async.wait_group 1;" ::: "memory")

__device__ __forceinline__ void ldsm4(uint32_t* r, uint32_t a) {
    asm volatile("ldmatrix.sync.aligned.m8n8.x4.shared.b16 {%0,%1,%2,%3}, [%4];"
                 : "=r"(r[0]), "=r"(r[1]), "=r"(r[2]), "=r"(r[3]) : "r"(a));
}
__device__ __forceinline__ void ldsm4t(uint32_t* r, uint32_t a) {
    asm volatile("ldmatrix.sync.aligned.m8n8.x4.trans.shared.b16 {%0,%1,%2,%3}, [%4];"
                 : "=r"(r[0]), "=r"(r[1]), "=r"(r[2]), "=r"(r[3]) : "r"(a));
}
__device__ __forceinline__ void mma_f16(float c[4], const uint32_t a[4],
                                        uint32_t b0, uint32_t b1) {
    asm volatile(
        "mma.sync.aligned.m16n8k16.row.col.f32.f16.f16.f32 "
        "{%0,%1,%2,%3}, {%4,%5,%6,%7}, {%8,%9}, {%0,%1,%2,%3};\n"
        : "+f"(c[0]), "+f"(c[1]), "+f"(c[2]), "+f"(c[3])
        : "r"(a[0]), "r"(a[1]), "r"(a[2]), "r"(a[3]), "r"(b0), "r"(b1));
}

// fast exp on FMA pipe
__device__ __forceinline__ float fast_exp(float x) {
    float t = x * 1.4426950408889634f;
    t = fmaxf(t, -126.0f);
    float r = t + 12582912.0f;
    float n = r - 12582912.0f;
    float f = t - n;
    float p = 1.33335581e-3f;
    p = fmaf(p, f, 9.61812910e-3f);
    p = fmaf(p, f, 5.55041087e-2f);
    p = fmaf(p, f, 2.40226507e-1f);
    p = fmaf(p, f, 6.93147182e-1f);
    p = fmaf(p, f, 1.0f);
    int ni = (int)n;
    return p * __int_as_float((ni + 127) << 23);
}

// ================= fp16 mma.sync GEMM (128x128 tile) =================
// 3-stage cp.async, frag double-buffer, one barrier per k-tile.
// EPI: 1=+bias f32, 2=relu->half, 3=+residual f32, 4=plain->half, 5=+bias->half
#define BK 64
#define ABYT (128*128)
#define STG  (2*ABYT)
#define SMEMB (3*STG)

__device__ __forceinline__ void stage_tile(uint32_t sa, const __half* Ag, int lda,
                                           const __half* Bg, int ldb, int tid) {
    #pragma unroll
    for (int p = 0; p < 4; p++) {
        int id = tid + p * 256;
        int row = id >> 3, c = id & 7;
        uint32_t off = (uint32_t)(row * 128 + c * 16);
        off ^= ((off >> 3) & 0x70);
        cp16(sa + off,        Ag + (size_t)row * lda + c * 8);
        cp16(sa + ABYT + off, Bg + (size_t)row * ldb + c * 8);
    }
}

template<int EPI>
__device__ __forceinline__ void hgemm_core(
    const __half* __restrict__ A, int lda,
    const __half* __restrict__ BT, int ldb,
    void* __restrict__ Cv, int ldc, int K, const float* __restrict__ aux)
{
    extern __shared__ __align__(16) char smc[];
    const uint32_t sbase = smem_u32(smc);
    const int tid  = threadIdx.x;
    const int lane = tid & 31;
    const int warp = tid >> 5;
    const int wm = (warp & 1) * 64;
    const int wn = (warp >> 1) * 32;
    const int g = lane >> 2;
    const int t = lane & 3;
    const size_t bm = (size_t)blockIdx.y * 128;
    const size_t bn = (size_t)blockIdx.x * 128;

    const __half* Ab = A  + bm * lda;
    const __half* Bb = BT + bn * ldb;
    const int ktiles = K >> 6;

    const int l16 = lane & 15;
    const uint32_t khb = (uint32_t)((lane >> 4) << 4);
    const uint32_t xr  = (uint32_t)((lane & 7) << 4);

    float acc[4][4][4];
    #pragma unroll
    for (int i = 0; i < 4; i++)
        #pragma unroll
        for (int j = 0; j < 4; j++)
            #pragma unroll
            for (int r = 0; r < 4; r++) acc[i][j][r] = 0.f;

    #pragma unroll
    for (int s = 0; s < 2; s++) {
        if (s < ktiles)
            stage_tile(sbase + s * STG, Ab + s * BK, lda, Bb + s * BK, ldb, tid);
        CP_COMMIT();
    }

    int cs = 0, is_ = 2;
    for (int kt = 0; kt < ktiles; kt++) {
        CP_WAIT1();
        __syncthreads();

        if (kt + 2 < ktiles)
            stage_tile(sbase + is_ * STG, Ab + (kt+2) * BK, lda,
                       Bb + (kt+2) * BK, ldb, tid);
        CP_COMMIT();

        const uint32_t as = sbase + cs * STG;
        const uint32_t abase = as + (uint32_t)((wm + l16) * 128);
        const uint32_t bbase = as + ABYT + (uint32_t)((wn + l16) * 128);

        uint32_t af[2][4][4], bf[2][2][4];
        {
            const uint32_t kb = khb;
            #pragma unroll
            for (int im = 0; im < 4; im++)
                ldsm4(af[0][im], abase + im*2048 + (kb ^ xr));
            #pragma unroll
            for (int p = 0; p < 2; p++)
                ldsm4(bf[0][p], bbase + p*2048 + (kb ^ xr));
        }
        #pragma unroll
        for (int kk = 0; kk < 4; kk++) {
            const int cur = kk & 1, nxt = cur ^ 1;
            if (kk < 3) {
                const uint32_t kb = (uint32_t)((kk+1) * 32) + khb;
                #pragma unroll
                for (int im = 0; im < 4; im++)
                    ldsm4(af[nxt][im], abase + im*2048 + (kb ^ xr));
                #pragma unroll
                for (int p = 0; p < 2; p++)
                    ldsm4(bf[nxt][p], bbase + p*2048 + (kb ^ xr));
            }
            #pragma unroll
            for (int im = 0; im < 4; im++)
                #pragma unroll
                for (int j = 0; j < 4; j++)
                    mma_f16(acc[im][j], af[cur][im],
                            bf[cur][j>>1][j&1], bf[cur][j>>1][2+(j&1)]);
        }
        cs = (cs == 2) ? 0 : cs + 1;
        is_ = (is_ == 2) ? 0 : is_ + 1;
    }

    #pragma unroll
    for (int im = 0; im < 4; im++) {
        #pragma unroll
        for (int half = 0; half < 2; half++) {
            size_t row = bm + wm + im*16 + g + half*8;
            #pragma unroll
            for (int in = 0; in < 4; in++) {
                size_t col = bn + wn + in*8 + 2*t;
                float v0 = acc[im][in][half*2 + 0];
                float v1 = acc[im][in][half*2 + 1];
                if (EPI == 2) {
                    v0 = fmaxf(v0, 0.f); v1 = fmaxf(v1, 0.f);
                    *(__half2*)((__half*)Cv + row*ldc + col) = __floats2half2_rn(v0, v1);
                } else if (EPI == 4) {
                    *(__half2*)((__half*)Cv + row*ldc + col) = __floats2half2_rn(v0, v1);
                } else if (EPI == 5) {
                    v0 += aux[col]; v1 += aux[col+1];
                    *(__half2*)((__half*)Cv + row*ldc + col) = __floats2half2_rn(v0, v1);
                } else {
                    if (EPI == 1) { v0 += aux[col]; v1 += aux[col+1]; }
                    else if (EPI == 3) { v0 += aux[row*ldc+col]; v1 += aux[row*ldc+col+1]; }
                    *(float2*)((float*)Cv + row*ldc + col) = make_float2(v0, v1);
                }
            }
        }
    }
}

template<int EPI>
__global__ __launch_bounds__(256, 2) void hgemm(
    const __half* __restrict__ A, const __half* __restrict__ BT, void* __restrict__ C,
    int N, int K, const float* __restrict__ aux)
{
    hgemm_core<EPI>(A, K, BT, K, C, N, K, aux);
}

// batched QK^T: per (b,h) 256x256x64 -> half scores (unscaled)
__global__ __launch_bounds__(256, 2) void qk_gemm(
    const __half* __restrict__ qkvh, __half* __restrict__ scoresh)
{
    const int z = blockIdx.z;
    const int b = z / NHEADS;
    const __half* A = qkvh + (size_t)(b*SEQ) * QKVN + (z % NHEADS)*DHEAD;
    const __half* B = A + DMODEL;
    __half* C = scoresh + (size_t)z * SEQ * SEQ;
    hgemm_core<4>(A, QKVN, B, QKVN, C, SEQ, DHEAD, nullptr);
}

// ================= 64x128 tile GEMM (wave balance: fc2 / O / wi / wo / qkv) =================
// 8 warps 2(M) x 4(N), warp tile 32x32; no frag double-buffer; 3 CTAs/SM.
// EPI: 1=+bias f32, 2=relu->half, 3=+residual f32, 4=plain->half
#define A64BYT (64*128)
#define STG64  (A64BYT + ABYT)     // 24576
#define SMEMB64 (3*STG64)          // 73728

__device__ __forceinline__ void stage_tile64(uint32_t sa, const __half* Ag, int lda,
                                             const __half* Bg, int ldb, int tid) {
    #pragma unroll
    for (int p = 0; p < 2; p++) {
        int id = tid + p * 256;
        int row = id >> 3, c = id & 7;
        uint32_t off = (uint32_t)(row * 128 + c * 16);
        off ^= ((off >> 3) & 0x70);
        cp16(sa + off, Ag + (size_t)row * lda + c * 8);
    }
    #pragma unroll
    for (int p = 0; p < 4; p++) {
        int id = tid + p * 256;
        int row = id >> 3, c = id & 7;
        uint32_t off = (uint32_t)(row * 128 + c * 16);
        off ^= ((off >> 3) & 0x70);
        cp16(sa + A64BYT + off, Bg + (size_t)row * ldb + c * 8);
    }
}

template<int EPI>
__global__ __launch_bounds__(256, 3) void hgemm_m64(
    const __half* __restrict__ A, const __half* __restrict__ BT, void* __restrict__ Cv,
    int N, int K, const float* __restrict__ aux)
{
    extern __shared__ __align__(16) char smc[];
    const uint32_t sbase = smem_u32(smc);
    const int tid  = threadIdx.x;
    const int lane = tid & 31;
    const int warp = tid >> 5;
    const int wm = (warp & 1) * 32;
    const int wn = (warp >> 1) * 32;
    const int g = lane >> 2;
    const int t = lane & 3;
    const size_t bm = (size_t)blockIdx.y * 64;
    const size_t bn = (size_t)blockIdx.x * 128;

    const __half* Ab = A  + bm * K;
    const __half* Bb = BT + bn * K;
    const int ktiles = K >> 6;

    const int l16 = lane & 15;
    const uint32_t khb = (uint32_t)((lane >> 4) << 4);
    const uint32_t xr  = (uint32_t)((lane & 7) << 4);

    float acc[2][4][4];
    #pragma unroll
    for (int i = 0; i < 2; i++)
        #pragma unroll
        for (int j = 0; j < 4; j++)
            #pragma unroll
            for (int r = 0; r < 4; r++) acc[i][j][r] = 0.f;

    #pragma unroll
    for (int s = 0; s < 2; s++) {
        if (s < ktiles)
            stage_tile64(sbase + s * STG64, Ab + s * BK, K, Bb + s * BK, K, tid);
        CP_COMMIT();
    }

    int cs = 0, is_ = 2;
    for (int kt = 0; kt < ktiles; kt++) {
        CP_WAIT1();
        __syncthreads();

        if (kt + 2 < ktiles)
            stage_tile64(sbase + is_ * STG64, Ab + (kt+2) * BK, K,
                         Bb + (kt+2) * BK, K, tid);
        CP_COMMIT();

        const uint32_t as = sbase + cs * STG64;
        const uint32_t abase = as + (uint32_t)((wm + l16) * 128);
        const uint32_t bbase = as + A64BYT + (uint32_t)((wn + l16) * 128);

        #pragma unroll
        for (int kk = 0; kk < 4; kk++) {
            const uint32_t kb = (uint32_t)(kk * 32) + khb;
            uint32_t af[2][4], bf[2][4];
            #pragma unroll
            for (int im = 0; im < 2; im++)
                ldsm4(af[im], abase + im*2048 + (kb ^ xr));
            #pragma unroll
            for (int p = 0; p < 2; p++)
                ldsm4(bf[p], bbase + p*2048 + (kb ^ xr));
            #pragma unroll
            for (int im = 0; im < 2; im++)
                #pragma unroll
                for (int j = 0; j < 4; j++)
                    mma_f16(acc[im][j], af[im],
                            bf[j>>1][j&1], bf[j>>1][2+(j&1)]);
        }
        cs = (cs == 2) ? 0 : cs + 1;
        is_ = (is_ == 2) ? 0 : is_ + 1;
    }

    #pragma unroll
    for (int im = 0; im < 2; im++) {
        #pragma unroll
        for (int half = 0; half < 2; half++) {
            size_t row = bm + wm + im*16 + g + half*8;
            #pragma unroll
            for (int in = 0; in < 4; in++) {
                size_t col = bn + wn + in*8 + 2*t;
                float v0 = acc[im][in][half*2 + 0];
                float v1 = acc[im][in][half*2 + 1];
                if (EPI == 2) {
                    v0 = fmaxf(v0, 0.f); v1 = fmaxf(v1, 0.f);
                    *(__half2*)((__half*)Cv + row*N + col) = __floats2half2_rn(v0, v1);
                } else if (EPI == 4) {
                    *(__half2*)((__half*)Cv + row*N + col) = __floats2half2_rn(v0, v1);
                } else {
                    if (EPI == 1) { v0 += aux[col]; v1 += aux[col+1]; }
                    else if (EPI == 3) { v0 += aux[row*N+col]; v1 += aux[row*N+col+1]; }
                    *(float2*)((float*)Cv + row*N + col) = make_float2(v0, v1);
                }
            }
        }
    }
}

// ================= 32x128 tile GEMM (skinny-M: fc1), EPI=5 =================
#define A32BYT (32*128)
#define STG32  (A32BYT + ABYT)
#define SMEMB32 (3*STG32)

__device__ __forceinline__ void stage_tile32(uint32_t sa, const __half* Ag, int lda,
                                             const __half* Bg, int ldb, int tid) {
    {
        int row = tid >> 3, c = tid & 7;
        uint32_t off = (uint32_t)(row * 128 + c * 16);
        off ^= ((off >> 3) & 0x70);
        cp16(sa + off, Ag + (size_t)row * lda + c * 8);
    }
    #pragma unroll
    for (int p = 0; p < 4; p++) {
        int id = tid + p * 256;
        int row = id >> 3, c = id & 7;
        uint32_t off = (uint32_t)(row * 128 + c * 16);
        off ^= ((off >> 3) & 0x70);
        cp16(sa + A32BYT + off, Bg + (size_t)row * ldb + c * 8);
    }
}

__global__ __launch_bounds__(256, 2) void hgemm_m32(
    const __half* __restrict__ A, const __half* __restrict__ BT, __half* __restrict__ C,
    int N, int K, const float* __restrict__ aux)
{
    extern __shared__ __align__(16) char smc[];
    const uint32_t sbase = smem_u32(smc);
    const int tid  = threadIdx.x;
    const int lane = tid & 31;
    const int warp = tid >> 5;
    const int wm = (warp & 1) * 16;
    const int wn = (warp >> 1) * 32;
    const int g = lane >> 2;
    const int t = lane & 3;
    const size_t bm = (size_t)blockIdx.y * 32;
    const size_t bn = (size_t)blockIdx.x * 128;

    const __half* Ab = A  + bm * K;
    const __half* Bb = BT + bn * K;
    const int ktiles = K >> 6;

    const int l16 = lane & 15;
    const uint32_t khb = (uint32_t)((lane >> 4) << 4);
    const uint32_t xr  = (uint32_t)((lane & 7) << 4);

    float acc[4][4];
    #pragma unroll
    for (int j = 0; j < 4; j++)
        #pragma unroll
        for (int r = 0; r < 4; r++) acc[j][r] = 0.f;

    #pragma unroll
    for (int s = 0; s < 2; s++) {
        if (s < ktiles)
            stage_tile32(sbase + s * STG32, Ab + s * BK, K, Bb + s * BK, K, tid);
        CP_COMMIT();
    }

    int cs = 0, is_ = 2;
    for (int kt = 0; kt < ktiles; kt++) {
        CP_WAIT1();
        __syncthreads();

        if (kt + 2 < ktiles)
            stage_tile32(sbase + is_ * STG32, Ab + (kt+2) * BK, K,
                         Bb + (kt+2) * BK, K, tid);
        CP_COMMIT();

        const uint32_t as = sbase + cs * STG32;
        const uint32_t abase = as + (uint32_t)((wm + l16) * 128);
        const uint32_t bbase = as + A32BYT + (uint32_t)((wn + l16) * 128);

        #pragma unroll
        for (int kk = 0; kk < 4; kk++) {
            const uint32_t kb = (uint32_t)(kk * 32) + khb;
            uint32_t af[4], bf[2][4];
            ldsm4(af, abase + (kb ^ xr));
            #pragma unroll
            for (int p = 0; p < 2; p++)
                ldsm4(bf[p], bbase + p*2048 + (kb ^ xr));
            #pragma unroll
            for (int j = 0; j < 4; j++)
                mma_f16(acc[j], af, bf[j>>1][j&1], bf[j>>1][2+(j&1)]);
        }
        cs = (cs == 2) ? 0 : cs + 1;
        is_ = (is_ == 2) ? 0 : is_ + 1;
    }

    #pragma unroll
    for (int half = 0; half < 2; half++) {
        size_t row = bm + wm + g + half*8;
        #pragma unroll
        for (int in = 0; in < 4; in++) {
            size_t col = bn + wn + in*8 + 2*t;
            float v0 = acc[in][half*2 + 0] + aux[col];
            float v1 = acc[in][half*2 + 1] + aux[col+1];
            *(__half2*)(C + row*N + col) = __floats2half2_rn(v0, v1);
        }
    }
}

// ================= AV tensor GEMM: ctx = probs @ V (3 CTAs/SM) =================
#define AV_A 16384
#define AVSTG 24576
#define AVSMEM (3*AVSTG)

__device__ __forceinline__ void av_stage(uint32_t sa, const __half* Ag,
                                         const __half* Vg, int tid) {
    #pragma unroll
    for (int p = 0; p < 4; p++) {
        int id = tid + p * 256;
        int row = id >> 3, c = id & 7;
        uint32_t off = (uint32_t)(row * 128 + c * 16);
        off ^= ((off >> 3) & 0x70);
        cp16(sa + off, Ag + (size_t)row * SEQ + c * 8);
    }
    #pragma unroll
    for (int p = 0; p < 2; p++) {
        int id = tid + p * 256;
        int row = id >> 3, c = id & 7;
        uint32_t off = (uint32_t)(row * 128 + c * 16);
        off ^= ((off >> 3) & 0x70);
        cp16(sa + AV_A + off, Vg + (size_t)row * QKVN + c * 8);
    }
}

__global__ __launch_bounds__(256, 3) void av_gemm(
    const __half* __restrict__ attnh, const __half* __restrict__ qkvh,
    __half* __restrict__ ctx)
{
    extern __shared__ __align__(16) char smc[];
    const uint32_t sbase = smem_u32(smc);
    const int tid  = threadIdx.x;
    const int lane = tid & 31;
    const int warp = tid >> 5;
    const int wm = (warp & 1) * 64;
    const int wn = (warp >> 1) * 16;
    const int z = blockIdx.y;
    const int b = z / NHEADS, h = z % NHEADS;
    const int bm = blockIdx.x * 128;

    const __half* Ab = attnh + ((size_t)z * SEQ + bm) * SEQ;
    const __half* Vb = qkvh + (size_t)(b*SEQ) * QKVN + 1536 + h*DHEAD;

    const int l16 = lane & 15;
    const uint32_t khb = (uint32_t)((lane >> 4) << 4);
    const uint32_t xr  = (uint32_t)((lane & 7) << 4);
    const int vrow = ((lane >> 3) & 1) * 8 + (lane & 7);
    const uint32_t vcolb = (uint32_t)(wn*2 + ((lane >> 4) << 4));

    float acc[4][2][4];
    #pragma unroll
    for (int i = 0; i < 4; i++)
        #pragma unroll
        for (int j = 0; j < 2; j++)
            #pragma unroll
            for (int r = 0; r < 4; r++) acc[i][j][r] = 0.f;

    #pragma unroll
    for (int s = 0; s < 2; s++) {
        av_stage(sbase + s * AVSTG, Ab + s * 64, Vb + (size_t)s * 64 * QKVN, tid);
        CP_COMMIT();
    }

    int cs = 0, is_ = 2;
    for (int kt = 0; kt < 4; kt++) {
        CP_WAIT1();
        __syncthreads();
        if (kt + 2 < 4)
            av_stage(sbase + is_ * AVSTG, Ab + (kt+2) * 64,
                     Vb + (size_t)(kt+2) * 64 * QKVN, tid);
        CP_COMMIT();

        const uint32_t as = sbase + cs * AVSTG;
        const uint32_t vs = as + AV_A;
        const uint32_t abase = as + (uint32_t)((wm + l16) * 128);
        #pragma unroll
        for (int kk = 0; kk < 4; kk++) {
            const uint32_t kb = (uint32_t)(kk * 32) + khb;
            uint32_t af[4][4], bv[4];
            #pragma unroll
            for (int im = 0; im < 4; im++)
                ldsm4(af[im], abase + im*2048 + (kb ^ xr));
            ldsm4t(bv, vs + (uint32_t)((kk*16 + vrow) * 128) + (vcolb ^ xr));
            #pragma unroll
            for (int im = 0; im < 4; im++) {
                mma_f16(acc[im][0], af[im], bv[0], bv[1]);
                mma_f16(acc[im][1], af[im], bv[2], bv[3]);
            }
        }
        cs = (cs == 2) ? 0 : cs + 1;
        is_ = (is_ == 2) ? 0 : is_ + 1;
    }

    const int g = lane >> 2, t = lane & 3;
    #pragma unroll
    for (int im = 0; im < 4; im++) {
        #pragma unroll
        for (int half = 0; half < 2; half++) {
            int row = bm + wm + im*16 + g + half*8;
            #pragma unroll
            for (int jn = 0; jn < 2; jn++) {
                int col = wn + jn*8 + 2*t;
                *(__half2*)(ctx + ((size_t)(b*SEQ + row))*DMODEL + h*DHEAD + col)
                    = __floats2half2_rn(acc[im][jn][half*2], acc[im][jn][half*2+1]);
            }
        }
    }
}

// ================= bbox einsum (tensor cores) + bias + softmax (3 CTAs/SM) =================
#define BB2_A   16384
#define BB2_B   32768
#define BB2_SC  (12*256*4)
#define BB2_RB  1536
#define BB2_SMEM (BB2_A + BB2_B + BB2_SC + BB2_RB)

__global__ __launch_bounds__(256, 3) void bbox_softmax2(
    const __half* __restrict__ qkvh, const float* __restrict__ bbox,
    const float* __restrict__ rel_bias, const int* __restrict__ bkt,
    const __half* __restrict__ scoresh, __half* __restrict__ attnh)
{
    const int b  = blockIdx.x;
    const int i0 = blockIdx.y * 8;
    extern __shared__ __align__(16) char smc[];
    const uint32_t sA = smem_u32(smc);
    const uint32_t sB = sA + BB2_A;
    float* sc  = (float*)(smc + BB2_A + BB2_B);
    float* rbs = sc + 12*256;
    const int tid = threadIdx.x, lane = tid & 31, warp = tid >> 5;

    for (int t = tid; t < 384; t += 256) rbs[t] = rel_bias[t];

    #pragma unroll
    for (int p = 0; p < 4; p++) {
        int id = tid + p*256;
        int c  = id & 7;
        int hr = (id >> 3) & 15;
        int i  = id >> 7;
        uint4 v = make_uint4(0u, 0u, 0u, 0u);
        if (hr < 12)
            v = *(const uint4*)(qkvh + ((size_t)(b*SEQ) + i0 + i) * QKVN + hr*DHEAD + c*8);
        uint32_t off = (uint32_t)(i*2048 + hr*128 + c*16);
        off ^= ((off >> 3) & 0x70);
        *(uint4*)(smc + off) = v;
    }

    const int l16 = lane & 15;
    const uint32_t khb = (uint32_t)((lane >> 4) << 4);
    const uint32_t xr  = (uint32_t)((l16 & 7) << 4);
    const int r0 = warp*32 + l16, r1 = r0 + 16;
    const uint32_t brow0 = (uint32_t)(r0*128), brx0 = (uint32_t)((r0 & 7) << 4);
    const uint32_t brow1 = (uint32_t)(r1*128), brx1 = (uint32_t)((r1 & 7) << 4);
    const int g = lane >> 2, t4 = lane & 3;

    for (int i = 0; i < 8; i++) {
        __syncthreads();
        const float* bb = bbox + (((size_t)(i0 + i) * SEQ) * BATCH + b) * DHEAD;
        #pragma unroll
        for (int p = 0; p < 8; p++) {
            int id = tid + p*256;
            int row = id >> 3, c = id & 7;
            const float4* s4 = (const float4*)(bb + (size_t)row * (BATCH*DHEAD) + c*8);
            float4 v0 = s4[0], v1 = s4[1];
            uint32_t off = (uint32_t)(row*128 + c*16);
            off ^= ((off >> 3) & 0x70);
            __half2* d = (__half2*)(smc + BB2_A + off);
            d[0] = __floats2half2_rn(v0.x, v0.y);
            d[1] = __floats2half2_rn(v0.z, v0.w);
            d[2] = __floats2half2_rn(v1.x, v1.y);
            d[3] = __floats2half2_rn(v1.z, v1.w);
        }
        __syncthreads();

        float acc[4][4];
        #pragma unroll
        for (int j = 0; j < 4; j++)
            #pragma unroll
            for (int r = 0; r < 4; r++) acc[j][r] = 0.f;

        const uint32_t abase = sA + (uint32_t)(i*2048) + (uint32_t)(l16*128);
        #pragma unroll
        for (int kk = 0; kk < 4; kk++) {
            const uint32_t kb = (uint32_t)(kk*32) + khb;
            uint32_t af[4], bf[2][4];
            ldsm4(af, abase + (kb ^ xr));
            ldsm4(bf[0], sB + brow0 + (kb ^ brx0));
            ldsm4(bf[1], sB + brow1 + (kb ^ brx1));
            #pragma unroll
            for (int j = 0; j < 4; j++)
                mma_f16(acc[j], af, bf[j>>1][j&1], bf[j>>1][2+(j&1)]);
        }
        #pragma unroll
        for (int j = 0; j < 4; j++) {
            int col = warp*32 + j*8 + 2*t4;
            sc[g*256 + col]     = acc[j][0];
            sc[g*256 + col + 1] = acc[j][1];
            if (g < 4) {
                sc[(g+8)*256 + col]     = acc[j][2];
                sc[(g+8)*256 + col + 1] = acc[j][3];
            }
        }
        __syncthreads();

        const int* bkrow = bkt + (i0 + i) * SEQ;
        #pragma unroll
        for (int rr = 0; rr < 2; rr++) {
            int h = warp + rr*8;
            if (h >= 12) break;
            const __half* qrow = scoresh + ((size_t)(b*NHEADS + h)*SEQ + i0 + i) * SEQ;
            float e[8], m = -1e30f;
            #pragma unroll
            for (int u = 0; u < 8; u++) {
                int col = lane + u*32;
                float s = sc[h*256 + col] + __half2float(qrow[col])
                          + rbs[bkrow[col]*NHEADS + h];
                s *= 0.125f;
                e[u] = s;
                m = fmaxf(m, s);
            }
            #pragma unroll
            for (int o = 16; o; o >>= 1) m = fmaxf(m, __shfl_xor_sync(0xffffffffu, m, o));
            float sum = 0.f;
            #pragma unroll
            for (int u = 0; u < 8; u++) { e[u] = fast_exp(e[u] - m); sum += e[u]; }
            #pragma unroll
            for (int o = 16; o; o >>= 1) sum += __shfl_xor_sync(0xffffffffu, sum, o);
            float inv = 1.f / sum;
            __half* op = attnh + ((size_t)(b*NHEADS + h)*SEQ + i0 + i) * SEQ;
            #pragma unroll
            for (int u = 0; u < 8; u++) op[lane + u*32] = __float2half_rn(e[u] * inv);
        }
    }
}

// ---------------- mega transpose ----------------
#define NJOBS 8
struct TJobs {
    const float* src[NJOBS];
    __half* dst[NJOBS];
    int R[NJOBS], C[NJOBS], start[NJOBS + 1];
};

__global__ __launch_bounds__(256) void mega_transpose(TJobs jobs)
{
    __shared__ float tsm[32][33];
    int bid = blockIdx.x;
    int j = 0;
    #pragma unroll
    for (int k = 1; k < NJOBS; k++)
        if (bid >= jobs.start[k]) j = k;
    int local = bid - jobs.start[j];
    int R = jobs.R[j], C = jobs.C[j];
    int tiles_x = C >> 5;
    int cx = (local % tiles_x) << 5;
    int ry = (local / tiles_x) << 5;
    const float* in = jobs.src[j];
    __half* out = jobs.dst[j];
    int x = threadIdx.x, y = threadIdx.y;
    #pragma unroll
    for (int i = 0; i < 32; i += 8)
        tsm[y + i][x] = in[(size_t)(ry + y + i) * C + cx + x];
    __syncthreads();
    #pragma unroll
    for (int i = 0; i < 32; i += 8)
        out[(size_t)(cx + y + i) * R + ry + x] = __float2half_rn(tsm[x][y + i]);
}

// ---------------- float -> half copy ----------------
__global__ __launch_bounds__(256) void round_kernel(
    const float* __restrict__ in, __half* __restrict__ out)
{
    size_t i = ((size_t)blockIdx.x * 256 + threadIdx.x) * 4;
    float4 v = *(const float4*)(in + i);
    __half2* o = (__half2*)(out + i);
    o[0] = __floats2half2_rn(v.x, v.y);
    o[1] = __floats2half2_rn(v.z, v.w);
}

// ---------------- relative-position bucket ----------------
__global__ void bucket_kernel(int* __restrict__ bkt) {
    int i = blockIdx.x, j = threadIdx.x;
    int rel = j - i;
    int base = (rel > 0) ? 16 : 0;
    int arel = rel < 0 ? -rel : rel;
    int v;
    if (arel < 8) {
        v = arel;
    } else {
        float t = logf((float)arel / 8.0f) / 2.772588722239781f * 8.0f;
        v = 8 + (int)t;
        if (v > 15) v = 15;
    }
    bkt[i*SEQ + j] = base + v;
}

// ---------------- depthwise 3x3 conv (half in) -> half ----------------
__global__ __launch_bounds__(128) void conv_kernel(
    const __half* __restrict__ h1, const float* __restrict__ cw,
    const float* __restrict__ cb, __half* __restrict__ out)
{
    int p  = blockIdx.x;
    int l  = p & 255;
    int bn = p >> 8;
    int ni = bn & 7;
    int bi = bn >> 3;
    int c  = threadIdx.x;

    float acc = cb[c];
    #pragma unroll
    for (int dn = -1; dn <= 1; dn++) {
        int nn = ni + dn;
        if (nn < 0 || nn >= NFRAMES) continue;
        #pragma unroll
        for (int dl = -1; dl <= 1; dl++) {
            int ll = l + dl;
            if (ll < 0 || ll >= SEQ) continue;
            float x = __half2float(h1[(size_t)(((bi*NFRAMES + nn)*SEQ) + ll) * ADC + c]);
            acc = fmaf(x, cw[c*9 + (dn+1)*3 + (dl+1)], acc);
        }
    }
    out[(size_t)p * ADC + c] = __float2half_rn(acc);
}

// ---------------- norms ----------------
__device__ __forceinline__ float blk_sum(float v, volatile float* red) {
    int tid = threadIdx.x;
    #pragma unroll
    for (int o = 16; o; o >>= 1) v += __shfl_xor_sync(0xffffffffu, v, o);
    if ((tid & 31) == 0) red[tid >> 5] = v;
    __syncthreads();
    if (tid == 0) {
        float s = 0.f;
        #pragma unroll
        for (int w = 0; w < 8; w++) s += red[w];
        red[8] = s;
    }
    __syncthreads();
    return red[8];
}

__global__ __launch_bounds__(256) void ln_res_rms_kernel(
    const float* __restrict__ x, const float* __restrict__ w,
    const float* __restrict__ bvec, const float* __restrict__ res,
    const float* __restrict__ w1,
    float* __restrict__ hs, __half* __restrict__ hn16)
{
    __shared__ float red[9];
    size_t base = (size_t)blockIdx.x * DMODEL;
    int t = threadIdx.x;
    float v0 = x[base+t], v1 = x[base+t+256], v2 = x[base+t+512];
    float mu = blk_sum(v0+v1+v2, red) * (1.f/DMODEL);
    __syncthreads();
    float d0 = v0-mu, d1 = v1-mu, d2 = v2-mu;
    float var = blk_sum(d0*d0 + d1*d1 + d2*d2, red) * (1.f/DMODEL);
    float inv = rsqrtf(var + 1e-5f);
    float o0 = d0*inv*w[t]     + bvec[t]     + res[base+t];
    float o1 = d1*inv*w[t+256] + bvec[t+256] + res[base+t+256];
    float o2 = d2*inv*w[t+512] + bvec[t+512] + res[base+t+512];
    hs[base+t    ] = o0;
    hs[base+t+256] = o1;
    hs[base+t+512] = o2;
    __syncthreads();
    float ms = blk_sum(o0*o0 + o1*o1 + o2*o2, red) * (1.f/DMODEL);
    float rinv = rsqrtf(ms + 1e-6f);
    hn16[base+t    ] = __float2half_rn(w1[t]    *o0*rinv);
    hn16[base+t+256] = __float2half_rn(w1[t+256]*o1*rinv);
    hn16[base+t+512] = __float2half_rn(w1[t+512]*o2*rinv);
}

__global__ __launch_bounds__(256) void rms_kernel(
    const float* __restrict__ x, const float* __restrict__ w, __half* __restrict__ out)
{
    __shared__ float red[9];
    size_t base = (size_t)blockIdx.x * DMODEL;
    int t = threadIdx.x;
    float v0 = x[base+t], v1 = x[base+t+256], v2 = x[base+t+512];
    float ms = blk_sum(v0*v0 + v1*v1 + v2*v2, red) * (1.f/DMODEL);
    float inv = rsqrtf(ms + 1e-6f);
    out[base+t    ] = __float2half_rn(w[t]    *v0*inv);
    out[base+t+256] = __float2half_rn(w[t+256]*v1*inv);
    out[base+t+512] = __float2half_rn(w[t+512]*v2*inv);
}

// ---------------- launch ----------------
extern "C" void kernel_launch(void* const* d_in, const int* in_sizes, int n_in,
                              void* d_out, int out_size)
{
    const float* hidden  = (const float*)d_in[0];
    const float* bbox    = (const float*)d_in[1];
    const float* fc1_w   = (const float*)d_in[2];
    const float* fc1_b   = (const float*)d_in[3];
    const float* conv_w  = (const float*)d_in[4];
    const float* conv_b  = (const float*)d_in[5];
    const float* fc2_w   = (const float*)d_in[6];
    const float* fc2_b   = (const float*)d_in[7];
    const float* ln_ad_w = (const float*)d_in[8];
    const float* ln_ad_b = (const float*)d_in[9];
    const float* ln1_w   = (const float*)d_in[10];
    const float* q_w     = (const float*)d_in[11];
    const float* k_w     = (const float*)d_in[12];
    const float* v_w     = (const float*)d_in[13];
    const float* o_w     = (const float*)d_in[14];
    const float* rel_b   = (const float*)d_in[15];
    const float* ln2_w   = (const float*)d_in[16];
    const float* wi_w    = (const float*)d_in[17];
    const float* wo_w    = (const float*)d_in[18];
    float* out = (float*)d_out;

    __half *h16, *h1h, *cv16, *hn16, *qkvh, *ctx16, *ff16, *attnh, *scoresh;
    __half *wtqkv, *wto, *wtwi, *wtwo, *wtf1, *wtf2;
    float *ad, *hs, *hs2;
    int* bkt;
    cudaGetSymbolAddress((void**)&h16,  g_h16);
    cudaGetSymbolAddress((void**)&h1h,  g_h1h);
    cudaGetSymbolAddress((void**)&cv16, g_cv16);
    cudaGetSymbolAddress((void**)&ad,   g_ad);
    cudaGetSymbolAddress((void**)&hs,   g_hs);
    cudaGetSymbolAddress((void**)&hn16, g_hn16);
    cudaGetSymbolAddress((void**)&qkvh, g_qkvh);
    cudaGetSymbolAddress((void**)&ctx16,g_ctx16);
    cudaGetSymbolAddress((void**)&hs2,  g_hs2);
    cudaGetSymbolAddress((void**)&scoresh, g_scoresh);
    cudaGetSymbolAddress((void**)&attnh,g_attnh);
    cudaGetSymbolAddress((void**)&ff16, g_ff16);
    cudaGetSymbolAddress((void**)&bkt,  g_bucket);
    cudaGetSymbolAddress((void**)&wtqkv,g_wt_qkv);
    cudaGetSymbolAddress((void**)&wto,  g_wt_o);
    cudaGetSymbolAddress((void**)&wtwi, g_wt_wi);
    cudaGetSymbolAddress((void**)&wtwo, g_wt_wo);
    cudaGetSymbolAddress((void**)&wtf1, g_wt_fc1);
    cudaGetSymbolAddress((void**)&wtf2, g_wt_fc2);

    cudaFuncSetAttribute(hgemm_m64<1>, cudaFuncAttributeMaxDynamicSharedMemorySize, SMEMB64);
    cudaFuncSetAttribute(hgemm_m64<2>, cudaFuncAttributeMaxDynamicSharedMemorySize, SMEMB64);
    cudaFuncSetAttribute(hgemm_m64<3>, cudaFuncAttributeMaxDynamicSharedMemorySize, SMEMB64);
    cudaFuncSetAttribute(hgemm_m64<4>, cudaFuncAttributeMaxDynamicSharedMemorySize, SMEMB64);
    cudaFuncSetAttribute(hgemm_m32, cudaFuncAttributeMaxDynamicSharedMemorySize, SMEMB32);
    cudaFuncSetAttribute(qk_gemm,  cudaFuncAttributeMaxDynamicSharedMemorySize, SMEMB);
    cudaFuncSetAttribute(av_gemm,  cudaFuncAttributeMaxDynamicSharedMemorySize, AVSMEM);
    cudaFuncSetAttribute(bbox_softmax2, cudaFuncAttributeMaxDynamicSharedMemorySize, BB2_SMEM);

    // build job table
    TJobs J;
    const float* srcs[NJOBS] = {fc1_w, fc2_w, q_w, k_w, v_w, o_w, wi_w, wo_w};
    __half* dsts[NJOBS] = {wtf1, wtf2, wtqkv, wtqkv + DMODEL*DMODEL,
                           wtqkv + 2*DMODEL*DMODEL, wto, wtwi, wtwo};
    int Rs[NJOBS] = {DMODEL, ADC, DMODEL, DMODEL, DMODEL, DMODEL, DMODEL, DFF};
    int Cs[NJOBS] = {ADC, DMODEL, DMODEL, DMODEL, DMODEL, DMODEL, DFF, DMODEL};
    int acc = 0;
    for (int j = 0; j < NJOBS; j++) {
        J.src[j] = srcs[j]; J.dst[j] = dsts[j];
        J.R[j] = Rs[j]; J.C[j] = Cs[j];
        J.start[j] = acc;
        acc += (Rs[j] >> 5) * (Cs[j] >> 5);
    }
    J.start[NJOBS] = acc;

    dim3 tb(32, 8);
    mega_transpose<<<acc, tb>>>(J);                                                   // 0
    round_kernel<<<ROWS*DMODEL/1024, 256>>>(hidden, h16);                             // 1
    bucket_kernel<<<SEQ, SEQ>>>(bkt);                                                 // 2
    hgemm_m32<<<dim3(1, 128), 256, SMEMB32>>>(h16, wtf1, h1h, ADC, DMODEL, fc1_b);    // 3
    conv_kernel<<<ROWS, ADC>>>(h1h, conv_w, conv_b, cv16);                            // 4
    hgemm_m64<1><<<dim3(6, 64), 256, SMEMB64>>>(cv16, wtf2, ad, DMODEL, ADC, fc2_b);  // 5
    ln_res_rms_kernel<<<ROWS, 256>>>(ad, ln_ad_w, ln_ad_b, hidden, ln1_w, hs, hn16);  // 6
    hgemm_m64<4><<<dim3(QKVN/128, 64), 256, SMEMB64>>>(hn16, wtqkv, qkvh, QKVN, DMODEL, nullptr);
    qk_gemm<<<dim3(2, 2, BATCH*NHEADS), 256, SMEMB>>>(qkvh, scoresh);
    bbox_softmax2<<<dim3(BATCH, SEQ/8), 256, BB2_SMEM>>>(qkvh, bbox, rel_b, bkt, scoresh, attnh);
    av_gemm<<<dim3(2, BATCH*NHEADS), 256, AVSMEM>>>(attnh, qkvh, ctx16);
    hgemm_m64<3><<<dim3(6, 64), 256, SMEMB64>>>(ctx16, wto, hs2, DMODEL, DMODEL, hs);
    rms_kernel<<<ROWS, 256>>>(hs2, ln2_w, hn16);
    hgemm_m64<2><<<dim3(24, 64), 256, SMEMB64>>>(hn16, wtwi, ff16, DFF, DMODEL, nullptr);
    hgemm_m64<3><<<dim3(6, 64), 256, SMEMB64>>>(ff16, wtwo, out, DMODEL, DFF, hs2);
}

// round 17
// speedup vs baseline: 1.0036x; 1.0036x over previous
#include <cuda_runtime.h>
#include <cuda_fp16.h>
#include <math.h>
#include <stdint.h>

// ---------------- problem constants ----------------
#define BATCH   16
#define NFRAMES 8
#define SEQ     256
#define DMODEL  768
#define NHEADS  12
#define DHEAD   64
#define DFF     3072
#define ADC     128
#define ROWS    (BATCH*SEQ) // 4096
#define QKVN    2304

// ---------------- scratch (device globals; no allocations) ----------------
__device__ __align__(16) __half g_h16 [ROWS*DMODEL];
__device__ __align__(16) __half g_h1h [ROWS*ADC];
__device__ __align__(16) __half g_cv16[ROWS*ADC];
__device__ __align__(16) float  g_ad  [ROWS*DMODEL];
__device__ __align__(16) float  g_hs  [ROWS*DMODEL];
__device__ __align__(16) __half g_hn16[ROWS*DMODEL];
__device__ __align__(16) __half g_qkvh[ROWS*QKVN];
__device__ __align__(16) __half g_ctx16[ROWS*DMODEL];
__device__ __align__(16) float  g_hs2 [ROWS*DMODEL];
__device__ __align__(16) __half g_scoresh[BATCH*NHEADS*SEQ*SEQ]; // raw QK^T half
__device__ __align__(16) __half g_attnh [BATCH*NHEADS*SEQ*SEQ];  // probs half
__device__ __align__(16) __half g_ff16[ROWS*DFF];
__device__ int g_bucket[SEQ*SEQ];
// fp16 transposed weights [N][K]
__device__ __align__(16) __half g_wt_qkv[QKVN*DMODEL];
__device__ __align__(16) __half g_wt_o  [DMODEL*DMODEL];
__device__ __align__(16) __half g_wt_wi [DFF*DMODEL];
__device__ __align__(16) __half g_wt_wo [DMODEL*DFF];
__device__ __align__(16) __half g_wt_fc1[ADC*DMODEL];
__device__ __align__(16) __half g_wt_fc2[DMODEL*ADC];

// ================= helpers =================
__device__ __forceinline__ uint32_t smem_u32(const void* p) {
    uint32_t a;
    asm("{ .reg .u64 t; cvta.to.shared.u64 t, %1; cvt.u32.u64 %0, t; }" : "=r"(a) : "l"(p));
    return a;
}
__device__ __forceinline__ void cp16(uint32_t s, const void* g) {
    asm volatile("cp.async.cg.shared.global [%0], [%1], 16;" :: "r"(s), "l"(g));
}
#define CP_COMMIT() asm volatile("cp.async.commit_group;" ::: "memory")
#define CP_WAIT1()  asm volatile("cp.async.wait_group 1;" ::: "memory")

__device__ __forceinline__ void ldsm4(uint32_t* r, uint32_t a) {
    asm volatile("ldmatrix.sync.aligned.m8n8.x4.shared.b16 {%0,%1,%2,%3}, [%4];"
                 : "=r"(r[0]), "=r"(r[1]), "=r"(r[2]), "=r"(r[3]) : "r"(a));
}
__device__ __forceinline__ void ldsm4t(uint32_t* r, uint32_t a) {
    asm volatile("ldmatrix.sync.aligned.m8n8.x4.trans.shared.b16 {%0,%1,%2,%3}, [%4];"
                 : "=r"(r[0]), "=r"(r[1]), "=r"(r[2]), "=r"(r[3]) : "r"(a));
}
__device__ __forceinline__ void mma_f16(float c[4], const uint32_t a[4],
                                        uint32_t b0, uint32_t b1) {
    asm volatile(
        "mma.sync.aligned.m16n8k16.row.col.f32.f16.f16.f32 "
        "{%0,%1,%2,%3}, {%4,%5,%6,%7}, {%8,%9}, {%0,%1,%2,%3};\n"
        : "+f"(c[0]), "+f"(c[1]), "+f"(c[2]), "+f"(c[3])
        : "r"(a[0]), "r"(a[1]), "r"(a[2]), "r"(a[3]), "r"(b0), "r"(b1));
}

// fast exp on FMA pipe
__device__ __forceinline__ float fast_exp(float x) {
    float t = x * 1.4426950408889634f;
    t = fmaxf(t, -126.0f);
    float r = t + 12582912.0f;
    float n = r - 12582912.0f;
    float f = t - n;
    float p = 1.33335581e-3f;
    p = fmaf(p, f, 9.61812910e-3f);
    p = fmaf(p, f, 5.55041087e-2f);
    p = fmaf(p, f, 2.40226507e-1f);
    p = fmaf(p, f, 6.93147182e-1f);
    p = fmaf(p, f, 1.0f);
    int ni = (int)n;
    return p * __int_as_float((ni + 127) << 23);
}

// ================= fp16 mma.sync GEMM (128x128 tile) =================
// 3-stage cp.async, frag double-buffer, one barrier per k-tile.
// EPI: 1=+bias f32, 2=relu->half, 3=+residual f32, 4=plain->half, 5=+bias->half
#define BK 64
#define ABYT (128*128)
#define STG  (2*ABYT)
#define SMEMB (3*STG)

__device__ __forceinline__ void stage_tile(uint32_t sa, const __half* Ag, int lda,
                                           const __half* Bg, int ldb, int tid) {
    #pragma unroll
    for (int p = 0; p < 4; p++) {
        int id = tid + p * 256;
        int row = id >> 3, c = id & 7;
        uint32_t off = (uint32_t)(row * 128 + c * 16);
        off ^= ((off >> 3) & 0x70);
        cp16(sa + off,        Ag + (size_t)row * lda + c * 8);
        cp16(sa + ABYT + off, Bg + (size_t)row * ldb + c * 8);
    }
}

template<int EPI>
__device__ __forceinline__ void hgemm_core(
    const __half* __restrict__ A, int lda,
    const __half* __restrict__ BT, int ldb,
    void* __restrict__ Cv, int ldc, int K, const float* __restrict__ aux)
{
    extern __shared__ __align__(16) char smc[];
    const uint32_t sbase = smem_u32(smc);
    const int tid  = threadIdx.x;
    const int lane = tid & 31;
    const int warp = tid >> 5;
    const int wm = (warp & 1) * 64;
    const int wn = (warp >> 1) * 32;
    const int g = lane >> 2;
    const int t = lane & 3;
    const size_t bm = (size_t)blockIdx.y * 128;
    const size_t bn = (size_t)blockIdx.x * 128;

    const __half* Ab = A  + bm * lda;
    const __half* Bb = BT + bn * ldb;
    const int ktiles = K >> 6;

    const int l16 = lane & 15;
    const uint32_t khb = (uint32_t)((lane >> 4) << 4);
    const uint32_t xr  = (uint32_t)((lane & 7) << 4);

    float acc[4][4][4];
    #pragma unroll
    for (int i = 0; i < 4; i++)
        #pragma unroll
        for (int j = 0; j < 4; j++)
            #pragma unroll
            for (int r = 0; r < 4; r++) acc[i][j][r] = 0.f;

    #pragma unroll
    for (int s = 0; s < 2; s++) {
        if (s < ktiles)
            stage_tile(sbase + s * STG, Ab + s * BK, lda, Bb + s * BK, ldb, tid);
        CP_COMMIT();
    }

    int cs = 0, is_ = 2;
    for (int kt = 0; kt < ktiles; kt++) {
        CP_WAIT1();
        __syncthreads();

        if (kt + 2 < ktiles)
            stage_tile(sbase + is_ * STG, Ab + (kt+2) * BK, lda,
                       Bb + (kt+2) * BK, ldb, tid);
        CP_COMMIT();

        const uint32_t as = sbase + cs * STG;
        const uint32_t abase = as + (uint32_t)((wm + l16) * 128);
        const uint32_t bbase = as + ABYT + (uint32_t)((wn + l16) * 128);

        uint32_t af[2][4][4], bf[2][2][4];
        {
            const uint32_t kb = khb;
            #pragma unroll
            for (int im = 0; im < 4; im++)
                ldsm4(af[0][im], abase + im*2048 + (kb ^ xr));
            #pragma unroll
            for (int p = 0; p < 2; p++)
                ldsm4(bf[0][p], bbase + p*2048 + (kb ^ xr));
        }
        #pragma unroll
        for (int kk = 0; kk < 4; kk++) {
            const int cur = kk & 1, nxt = cur ^ 1;
            if (kk < 3) {
                const uint32_t kb = (uint32_t)((kk+1) * 32) + khb;
                #pragma unroll
                for (int im = 0; im < 4; im++)
                    ldsm4(af[nxt][im], abase + im*2048 + (kb ^ xr));
                #pragma unroll
                for (int p = 0; p < 2; p++)
                    ldsm4(bf[nxt][p], bbase + p*2048 + (kb ^ xr));
            }
            #pragma unroll
            for (int im = 0; im < 4; im++)
                #pragma unroll
                for (int j = 0; j < 4; j++)
                    mma_f16(acc[im][j], af[cur][im],
                            bf[cur][j>>1][j&1], bf[cur][j>>1][2+(j&1)]);
        }
        cs = (cs == 2) ? 0 : cs + 1;
        is_ = (is_ == 2) ? 0 : is_ + 1;
    }

    #pragma unroll
    for (int im = 0; im < 4; im++) {
        #pragma unroll
        for (int half = 0; half < 2; half++) {
            size_t row = bm + wm + im*16 + g + half*8;
            #pragma unroll
            for (int in = 0; in < 4; in++) {
                size_t col = bn + wn + in*8 + 2*t;
                float v0 = acc[im][in][half*2 + 0];
                float v1 = acc[im][in][half*2 + 1];
                if (EPI == 2) {
                    v0 = fmaxf(v0, 0.f); v1 = fmaxf(v1, 0.f);
                    *(__half2*)((__half*)Cv + row*ldc + col) = __floats2half2_rn(v0, v1);
                } else if (EPI == 4) {
                    *(__half2*)((__half*)Cv + row*ldc + col) = __floats2half2_rn(v0, v1);
                } else if (EPI == 5) {
                    v0 += aux[col]; v1 += aux[col+1];
                    *(__half2*)((__half*)Cv + row*ldc + col) = __floats2half2_rn(v0, v1);
                } else {
                    if (EPI == 1) { v0 += aux[col]; v1 += aux[col+1]; }
                    else if (EPI == 3) { v0 += aux[row*ldc+col]; v1 += aux[row*ldc+col+1]; }
                    *(float2*)((float*)Cv + row*ldc + col) = make_float2(v0, v1);
                }
            }
        }
    }
}

template<int EPI>
__global__ __launch_bounds__(256, 2) void hgemm(
    const __half* __restrict__ A, const __half* __restrict__ BT, void* __restrict__ C,
    int N, int K, const float* __restrict__ aux)
{
    hgemm_core<EPI>(A, K, BT, K, C, N, K, aux);
}

// batched QK^T: per (b,h) 256x256x64 -> half scores (unscaled)
__global__ __launch_bounds__(256, 2) void qk_gemm(
    const __half* __restrict__ qkvh, __half* __restrict__ scoresh)
{
    const int z = blockIdx.z;
    const int b = z / NHEADS;
    const __half* A = qkvh + (size_t)(b*SEQ) * QKVN + (z % NHEADS)*DHEAD;
    const __half* B = A + DMODEL;
    __half* C = scoresh + (size_t)z * SEQ * SEQ;
    hgemm_core<4>(A, QKVN, B, QKVN, C, SEQ, DHEAD, nullptr);
}

// ================= 64x128 tile GEMM (wave balance: fc2 / O / wi / wo) =================
#define A64BYT (64*128)
#define STG64  (A64BYT + ABYT)     // 24576
#define SMEMB64 (3*STG64)          // 73728

__device__ __forceinline__ void stage_tile64(uint32_t sa, const __half* Ag, int lda,
                                             const __half* Bg, int ldb, int tid) {
    #pragma unroll
    for (int p = 0; p < 2; p++) {
        int id = tid + p * 256;
        int row = id >> 3, c = id & 7;
        uint32_t off = (uint32_t)(row * 128 + c * 16);
        off ^= ((off >> 3) & 0x70);
        cp16(sa + off, Ag + (size_t)row * lda + c * 8);
    }
    #pragma unroll
    for (int p = 0; p < 4; p++) {
        int id = tid + p * 256;
        int row = id >> 3, c = id & 7;
        uint32_t off = (uint32_t)(row * 128 + c * 16);
        off ^= ((off >> 3) & 0x70);
        cp16(sa + A64BYT + off, Bg + (size_t)row * ldb + c * 8);
    }
}

template<int EPI>
__global__ __launch_bounds__(256, 3) void hgemm_m64(
    const __half* __restrict__ A, const __half* __restrict__ BT, void* __restrict__ Cv,
    int N, int K, const float* __restrict__ aux)
{
    extern __shared__ __align__(16) char smc[];
    const uint32_t sbase = smem_u32(smc);
    const int tid  = threadIdx.x;
    const int lane = tid & 31;
    const int warp = tid >> 5;
    const int wm = (warp & 1) * 32;
    const int wn = (warp >> 1) * 32;
    const int g = lane >> 2;
    const int t = lane & 3;
    const size_t bm = (size_t)blockIdx.y * 64;
    const size_t bn = (size_t)blockIdx.x * 128;

    const __half* Ab = A  + bm * K;
    const __half* Bb = BT + bn * K;
    const int ktiles = K >> 6;

    const int l16 = lane & 15;
    const uint32_t khb = (uint32_t)((lane >> 4) << 4);
    const uint32_t xr  = (uint32_t)((lane & 7) << 4);

    float acc[2][4][4];
    #pragma unroll
    for (int i = 0; i < 2; i++)
        #pragma unroll
        for (int j = 0; j < 4; j++)
            #pragma unroll
            for (int r = 0; r < 4; r++) acc[i][j][r] = 0.f;

    #pragma unroll
    for (int s = 0; s < 2; s++) {
        if (s < ktiles)
            stage_tile64(sbase + s * STG64, Ab + s * BK, K, Bb + s * BK, K, tid);
        CP_COMMIT();
    }

    int cs = 0, is_ = 2;
    for (int kt = 0; kt < ktiles; kt++) {
        CP_WAIT1();
        __syncthreads();

        if (kt + 2 < ktiles)
            stage_tile64(sbase + is_ * STG64, Ab + (kt+2) * BK, K,
                         Bb + (kt+2) * BK, K, tid);
        CP_COMMIT();

        const uint32_t as = sbase + cs * STG64;
        const uint32_t abase = as + (uint32_t)((wm + l16) * 128);
        const uint32_t bbase = as + A64BYT + (uint32_t)((wn + l16) * 128);

        #pragma unroll
        for (int kk = 0; kk < 4; kk++) {
            const uint32_t kb = (uint32_t)(kk * 32) + khb;
            uint32_t af[2][4], bf[2][4];
            #pragma unroll
            for (int im = 0; im < 2; im++)
                ldsm4(af[im], abase + im*2048 + (kb ^ xr));
            #pragma unroll
            for (int p = 0; p < 2; p++)
                ldsm4(bf[p], bbase + p*2048 + (kb ^ xr));
            #pragma unroll
            for (int im = 0; im < 2; im++)
                #pragma unroll
                for (int j = 0; j < 4; j++)
                    mma_f16(acc[im][j], af[im],
                            bf[j>>1][j&1], bf[j>>1][2+(j&1)]);
        }
        cs = (cs == 2) ? 0 : cs + 1;
        is_ = (is_ == 2) ? 0 : is_ + 1;
    }

    #pragma unroll
    for (int im = 0; im < 2; im++) {
        #pragma unroll
        for (int half = 0; half < 2; half++) {
            size_t row = bm + wm + im*16 + g + half*8;
            #pragma unroll
            for (int in = 0; in < 4; in++) {
                size_t col = bn + wn + in*8 + 2*t;
                float v0 = acc[im][in][half*2 + 0];
                float v1 = acc[im][in][half*2 + 1];
                if (EPI == 2) {
                    v0 = fmaxf(v0, 0.f); v1 = fmaxf(v1, 0.f);
                    *(__half2*)((__half*)Cv + row*N + col) = __floats2half2_rn(v0, v1);
                } else if (EPI == 4) {
                    *(__half2*)((__half*)Cv + row*N + col) = __floats2half2_rn(v0, v1);
                } else {
                    if (EPI == 1) { v0 += aux[col]; v1 += aux[col+1]; }
                    else if (EPI == 3) { v0 += aux[row*N+col]; v1 += aux[row*N+col+1]; }
                    *(float2*)((float*)Cv + row*N + col) = make_float2(v0, v1);
                }
            }
        }
    }
}

// ================= 16x128 tile GEMM (skinny-M: fc1), EPI = +bias->half =================
// 8 warps 1(M) x 8(N), warp tile 16x16; grid (1, 256); 3 CTAs/SM.
#define A16BYT (16*128)
#define STG16  (A16BYT + ABYT)     // 2048 + 16384 = 18432
#define SMEMB16 (3*STG16)          // 55296

__device__ __forceinline__ void stage_tile16(uint32_t sa, const __half* Ag, int lda,
                                             const __half* Bg, int ldb, int tid) {
    if (tid < 128) {
        int row = tid >> 3, c = tid & 7;
        uint32_t off = (uint32_t)(row * 128 + c * 16);
        off ^= ((off >> 3) & 0x70);
        cp16(sa + off, Ag + (size_t)row * lda + c * 8);
    }
    #pragma unroll
    for (int p = 0; p < 4; p++) {
        int id = tid + p * 256;
        int row = id >> 3, c = id & 7;
        uint32_t off = (uint32_t)(row * 128 + c * 16);
        off ^= ((off >> 3) & 0x70);
        cp16(sa + A16BYT + off, Bg + (size_t)row * ldb + c * 8);
    }
}

__global__ __launch_bounds__(256, 3) void hgemm_m16(
    const __half* __restrict__ A, const __half* __restrict__ BT, __half* __restrict__ C,
    int N, int K, const float* __restrict__ aux)
{
    extern __shared__ __align__(16) char smc[];
    const uint32_t sbase = smem_u32(smc);
    const int tid  = threadIdx.x;
    const int lane = tid & 31;
    const int warp = tid >> 5;
    const int wn = warp * 16;
    const int g = lane >> 2;
    const int t = lane & 3;
    const size_t bm = (size_t)blockIdx.y * 16;
    const size_t bn = (size_t)blockIdx.x * 128;

    const __half* Ab = A  + bm * K;
    const __half* Bb = BT + bn * K;
    const int ktiles = K >> 6;

    const int l16 = lane & 15;
    const uint32_t khb = (uint32_t)((lane >> 4) << 4);
    const uint32_t xr  = (uint32_t)((lane & 7) << 4);

    float acc[2][4];
    #pragma unroll
    for (int j = 0; j < 2; j++)
        #pragma unroll
        for (int r = 0; r < 4; r++) acc[j][r] = 0.f;

    #pragma unroll
    for (int s = 0; s < 2; s++) {
        if (s < ktiles)
            stage_tile16(sbase + s * STG16, Ab + s * BK, K, Bb + s * BK, K, tid);
        CP_COMMIT();
    }

    int cs = 0, is_ = 2;
    for (int kt = 0; kt < ktiles; kt++) {
        CP_WAIT1();
        __syncthreads();

        if (kt + 2 < ktiles)
            stage_tile16(sbase + is_ * STG16, Ab + (kt+2) * BK, K,
                         Bb + (kt+2) * BK, K, tid);
        CP_COMMIT();

        const uint32_t as = sbase + cs * STG16;
        const uint32_t abase = as + (uint32_t)(l16 * 128);
        const uint32_t bbase = as + A16BYT + (uint32_t)((wn + l16) * 128);

        #pragma unroll
        for (int kk = 0; kk < 4; kk++) {
            const uint32_t kb = (uint32_t)(kk * 32) + khb;
            uint32_t af[4], bf[4];
            ldsm4(af, abase + (kb ^ xr));
            ldsm4(bf, bbase + (kb ^ xr));
            #pragma unroll
            for (int j = 0; j < 2; j++)
                mma_f16(acc[j], af, bf[j], bf[2+j]);
        }
        cs = (cs == 2) ? 0 : cs + 1;
        is_ = (is_ == 2) ? 0 : is_ + 1;
    }

    #pragma unroll
    for (int half = 0; half < 2; half++) {
        size_t row = bm + g + half*8;
        #pragma unroll
        for (int j = 0; j < 2; j++) {
            size_t col = bn + wn + j*8 + 2*t;
            float v0 = acc[j][half*2 + 0] + aux[col];
            float v1 = acc[j][half*2 + 1] + aux[col+1];
            *(__half2*)(C + row*N + col) = __floats2half2_rn(v0, v1);
        }
    }
}

// ================= AV tensor GEMM: ctx = probs @ V (3 CTAs/SM) =================
#define AV_A 16384
#define AVSTG 24576
#define AVSMEM (3*AVSTG)

__device__ __forceinline__ void av_stage(uint32_t sa, const __half* Ag,
                                         const __half* Vg, int tid) {
    #pragma unroll
    for (int p = 0; p < 4; p++) {
        int id = tid + p * 256;
        int row = id >> 3, c = id & 7;
        uint32_t off = (uint32_t)(row * 128 + c * 16);
        off ^= ((off >> 3) & 0x70);
        cp16(sa + off, Ag + (size_t)row * SEQ + c * 8);
    }
    #pragma unroll
    for (int p = 0; p < 2; p++) {
        int id = tid + p * 256;
        int row = id >> 3, c = id & 7;
        uint32_t off = (uint32_t)(row * 128 + c * 16);
        off ^= ((off >> 3) & 0x70);
        cp16(sa + AV_A + off, Vg + (size_t)row * QKVN + c * 8);
    }
}

__global__ __launch_bounds__(256, 3) void av_gemm(
    const __half* __restrict__ attnh, const __half* __restrict__ qkvh,
    __half* __restrict__ ctx)
{
    extern __shared__ __align__(16) char smc[];
    const uint32_t sbase = smem_u32(smc);
    const int tid  = threadIdx.x;
    const int lane = tid & 31;
    const int warp = tid >> 5;
    const int wm = (warp & 1) * 64;
    const int wn = (warp >> 1) * 16;
    const int z = blockIdx.y;
    const int b = z / NHEADS, h = z % NHEADS;
    const int bm = blockIdx.x * 128;

    const __half* Ab = attnh + ((size_t)z * SEQ + bm) * SEQ;
    const __half* Vb = qkvh + (size_t)(b*SEQ) * QKVN + 1536 + h*DHEAD;

    const int l16 = lane & 15;
    const uint32_t khb = (uint32_t)((lane >> 4) << 4);
    const uint32_t xr  = (uint32_t)((lane & 7) << 4);
    const int vrow = ((lane >> 3) & 1) * 8 + (lane & 7);
    const uint32_t vcolb = (uint32_t)(wn*2 + ((lane >> 4) << 4));

    float acc[4][2][4];
    #pragma unroll
    for (int i = 0; i < 4; i++)
        #pragma unroll
        for (int j = 0; j < 2; j++)
            #pragma unroll
            for (int r = 0; r < 4; r++) acc[i][j][r] = 0.f;

    #pragma unroll
    for (int s = 0; s < 2; s++) {
        av_stage(sbase + s * AVSTG, Ab + s * 64, Vb + (size_t)s * 64 * QKVN, tid);
        CP_COMMIT();
    }

    int cs = 0, is_ = 2;
    for (int kt = 0; kt < 4; kt++) {
        CP_WAIT1();
        __syncthreads();
        if (kt + 2 < 4)
            av_stage(sbase + is_ * AVSTG, Ab + (kt+2) * 64,
                     Vb + (size_t)(kt+2) * 64 * QKVN, tid);
        CP_COMMIT();

        const uint32_t as = sbase + cs * AVSTG;
        const uint32_t vs = as + AV_A;
        const uint32_t abase = as + (uint32_t)((wm + l16) * 128);
        #pragma unroll
        for (int kk = 0; kk < 4; kk++) {
            const uint32_t kb = (uint32_t)(kk * 32) + khb;
            uint32_t af[4][4], bv[4];
            #pragma unroll
            for (int im = 0; im < 4; im++)
                ldsm4(af[im], abase + im*2048 + (kb ^ xr));
            ldsm4t(bv, vs + (uint32_t)((kk*16 + vrow) * 128) + (vcolb ^ xr));
            #pragma unroll
            for (int im = 0; im < 4; im++) {
                mma_f16(acc[im][0], af[im], bv[0], bv[1]);
                mma_f16(acc[im][1], af[im], bv[2], bv[3]);
            }
        }
        cs = (cs == 2) ? 0 : cs + 1;
        is_ = (is_ == 2) ? 0 : is_ + 1;
    }

    const int g = lane >> 2, t = lane & 3;
    #pragma unroll
    for (int im = 0; im < 4; im++) {
        #pragma unroll
        for (int half = 0; half < 2; half++) {
            int row = bm + wm + im*16 + g + half*8;
            #pragma unroll
            for (int jn = 0; jn < 2; jn++) {
                int col = wn + jn*8 + 2*t;
                *(__half2*)(ctx + ((size_t)(b*SEQ + row))*DMODEL + h*DHEAD + col)
                    = __floats2half2_rn(acc[im][jn][half*2], acc[im][jn][half*2+1]);
            }
        }
    }
}

// ================= bbox einsum (tensor cores) + bias + softmax (3 CTAs/SM) =================
#define BB2_A   16384
#define BB2_B   32768
#define BB2_SC  (12*256*4)
#define BB2_RB  1536
#define BB2_SMEM (BB2_A + BB2_B + BB2_SC + BB2_RB)

__global__ __launch_bounds__(256, 3) void bbox_softmax2(
    const __half* __restrict__ qkvh, const float* __restrict__ bbox,
    const float* __restrict__ rel_bias, const int* __restrict__ bkt,
    const __half* __restrict__ scoresh, __half* __restrict__ attnh)
{
    const int b  = blockIdx.x;
    const int i0 = blockIdx.y * 8;
    extern __shared__ __align__(16) char smc[];
    const uint32_t sA = smem_u32(smc);
    const uint32_t sB = sA + BB2_A;
    float* sc  = (float*)(smc + BB2_A + BB2_B);
    float* rbs = sc + 12*256;
    const int tid = threadIdx.x, lane = tid & 31, warp = tid >> 5;

    for (int t = tid; t < 384; t += 256) rbs[t] = rel_bias[t];

    #pragma unroll
    for (int p = 0; p < 4; p++) {
        int id = tid + p*256;
        int c  = id & 7;
        int hr = (id >> 3) & 15;
        int i  = id >> 7;
        uint4 v = make_uint4(0u, 0u, 0u, 0u);
        if (hr < 12)
            v = *(const uint4*)(qkvh + ((size_t)(b*SEQ) + i0 + i) * QKVN + hr*DHEAD + c*8);
        uint32_t off = (uint32_t)(i*2048 + hr*128 + c*16);
        off ^= ((off >> 3) & 0x70);
        *(uint4*)(smc + off) = v;
    }

    const int l16 = lane & 15;
    const uint32_t khb = (uint32_t)((lane >> 4) << 4);
    const uint32_t xr  = (uint32_t)((l16 & 7) << 4);
    const int r0 = warp*32 + l16, r1 = r0 + 16;
    const uint32_t brow0 = (uint32_t)(r0*128), brx0 = (uint32_t)((r0 & 7) << 4);
    const uint32_t brow1 = (uint32_t)(r1*128), brx1 = (uint32_t)((r1 & 7) << 4);
    const int g = lane >> 2, t4 = lane & 3;

    for (int i = 0; i < 8; i++) {
        __syncthreads();
        const float* bb = bbox + (((size_t)(i0 + i) * SEQ) * BATCH + b) * DHEAD;
        #pragma unroll
        for (int p = 0; p < 8; p++) {
            int id = tid + p*256;
            int row = id >> 3, c = id & 7;
            const float4* s4 = (const float4*)(bb + (size_t)row * (BATCH*DHEAD) + c*8);
            float4 v0 = s4[0], v1 = s4[1];
            uint32_t off = (uint32_t)(row*128 + c*16);
            off ^= ((off >> 3) & 0x70);
            __half2* d = (__half2*)(smc + BB2_A + off);
            d[0] = __floats2half2_rn(v0.x, v0.y);
            d[1] = __floats2half2_rn(v0.z, v0.w);
            d[2] = __floats2half2_rn(v1.x, v1.y);
            d[3] = __floats2half2_rn(v1.z, v1.w);
        }
        __syncthreads();

        float acc[4][4];
        #pragma unroll
        for (int j = 0; j < 4; j++)
            #pragma unroll
            for (int r = 0; r < 4; r++) acc[j][r] = 0.f;

        const uint32_t abase = sA + (uint32_t)(i*2048) + (uint32_t)(l16*128);
        #pragma unroll
        for (int kk = 0; kk < 4; kk++) {
            const uint32_t kb = (uint32_t)(kk*32) + khb;
            uint32_t af[4], bf[2][4];
            ldsm4(af, abase + (kb ^ xr));
            ldsm4(bf[0], sB + brow0 + (kb ^ brx0));
            ldsm4(bf[1], sB + brow1 + (kb ^ brx1));
            #pragma unroll
            for (int j = 0; j < 4; j++)
                mma_f16(acc[j], af, bf[j>>1][j&1], bf[j>>1][2+(j&1)]);
        }
        #pragma unroll
        for (int j = 0; j < 4; j++) {
            int col = warp*32 + j*8 + 2*t4;
            sc[g*256 + col]     = acc[j][0];
            sc[g*256 + col + 1] = acc[j][1];
            if (g < 4) {
                sc[(g+8)*256 + col]     = acc[j][2];
                sc[(g+8)*256 + col + 1] = acc[j][3];
            }
        }
        __syncthreads();

        const int* bkrow = bkt + (i0 + i) * SEQ;
        #pragma unroll
        for (int rr = 0; rr < 2; rr++) {
            int h = warp + rr*8;
            if (h >= 12) break;
            const __half* qrow = scoresh + ((size_t)(b*NHEADS + h)*SEQ + i0 + i) * SEQ;
            float e[8], m = -1e30f;
            #pragma unroll
            for (int u = 0; u < 8; u++) {
                int col = lane + u*32;
                float s = sc[h*256 + col] + __half2float(qrow[col])
                          + rbs[bkrow[col]*NHEADS + h];
                s *= 0.125f;
                e[u] = s;
                m = fmaxf(m, s);
            }
            #pragma unroll
            for (int o = 16; o; o >>= 1) m = fmaxf(m, __shfl_xor_sync(0xffffffffu, m, o));
            float sum = 0.f;
            #pragma unroll
            for (int u = 0; u < 8; u++) { e[u] = fast_exp(e[u] - m); sum += e[u]; }
            #pragma unroll
            for (int o = 16; o; o >>= 1) sum += __shfl_xor_sync(0xffffffffu, sum, o);
            float inv = 1.f / sum;
            __half* op = attnh + ((size_t)(b*NHEADS + h)*SEQ + i0 + i) * SEQ;
            #pragma unroll
            for (int u = 0; u < 8; u++) op[lane + u*32] = __float2half_rn(e[u] * inv);
        }
    }
}

// ---------------- mega transpose ----------------
#define NJOBS 8
struct TJobs {
    const float* src[NJOBS];
    __half* dst[NJOBS];
    int R[NJOBS], C[NJOBS], start[NJOBS + 1];
};

__global__ __launch_bounds__(256) void mega_transpose(TJobs jobs)
{
    __shared__ float tsm[32][33];
    int bid = blockIdx.x;
    int j = 0;
    #pragma unroll
    for (int k = 1; k < NJOBS; k++)
        if (bid >= jobs.start[k]) j = k;
    int local = bid - jobs.start[j];
    int R = jobs.R[j], C = jobs.C[j];
    int tiles_x = C >> 5;
    int cx = (local % tiles_x) << 5;
    int ry = (local / tiles_x) << 5;
    const float* in = jobs.src[j];
    __half* out = jobs.dst[j];
    int x = threadIdx.x, y = threadIdx.y;
    #pragma unroll
    for (int i = 0; i < 32; i += 8)
        tsm[y + i][x] = in[(size_t)(ry + y + i) * C + cx + x];
    __syncthreads();
    #pragma unroll
    for (int i = 0; i < 32; i += 8)
        out[(size_t)(cx + y + i) * R + ry + x] = __float2half_rn(tsm[x][y + i]);
}

// ---------------- prep: round hidden -> half  +  relative-position bucket ----------------
#define ROUND_BLOCKS (ROWS*DMODEL/1024)
__global__ __launch_bounds__(256) void prep_kernel(
    const float* __restrict__ in, __half* __restrict__ out, int* __restrict__ bkt)
{
    int bid = blockIdx.x;
    if (bid < ROUND_BLOCKS) {
        size_t i = ((size_t)bid * 256 + threadIdx.x) * 4;
        float4 v = *(const float4*)(in + i);
        __half2* o = (__half2*)(out + i);
        o[0] = __floats2half2_rn(v.x, v.y);
        o[1] = __floats2half2_rn(v.z, v.w);
    } else {
        int i = bid - ROUND_BLOCKS;   // 0..255
        int j = threadIdx.x;          // 0..255
        int rel = j - i;
        int base = (rel > 0) ? 16 : 0;
        int arel = rel < 0 ? -rel : rel;
        int v;
        if (arel < 8) {
            v = arel;
        } else {
            float t = logf((float)arel / 8.0f) / 2.772588722239781f * 8.0f;
            v = 8 + (int)t;
            if (v > 15) v = 15;
        }
        bkt[i*SEQ + j] = base + v;
    }
}

// ---------------- depthwise 3x3 conv (half in) -> half ----------------
__global__ __launch_bounds__(128) void conv_kernel(
    const __half* __restrict__ h1, const float* __restrict__ cw,
    const float* __restrict__ cb, __half* __restrict__ out)
{
    int p  = blockIdx.x;
    int l  = p & 255;
    int bn = p >> 8;
    int ni = bn & 7;
    int bi = bn >> 3;
    int c  = threadIdx.x;

    float acc = cb[c];
    #pragma unroll
    for (int dn = -1; dn <= 1; dn++) {
        int nn = ni + dn;
        if (nn < 0 || nn >= NFRAMES) continue;
        #pragma unroll
        for (int dl = -1; dl <= 1; dl++) {
            int ll = l + dl;
            if (ll < 0 || ll >= SEQ) continue;
            float x = __half2float(h1[(size_t)(((bi*NFRAMES + nn)*SEQ) + ll) * ADC + c]);
            acc = fmaf(x, cw[c*9 + (dn+1)*3 + (dl+1)], acc);
        }
    }
    out[(size_t)p * ADC + c] = __float2half_rn(acc);
}

// ---------------- norms ----------------
__device__ __forceinline__ float blk_sum(float v, volatile float* red) {
    int tid = threadIdx.x;
    #pragma unroll
    for (int o = 16; o; o >>= 1) v += __shfl_xor_sync(0xffffffffu, v, o);
    if ((tid & 31) == 0) red[tid >> 5] = v;
    __syncthreads();
    if (tid == 0) {
        float s = 0.f;
        #pragma unroll
        for (int w = 0; w < 8; w++) s += red[w];
        red[8] = s;
    }
    __syncthreads();
    return red[8];
}

__global__ __launch_bounds__(256) void ln_res_rms_kernel(
    const float* __restrict__ x, const float* __restrict__ w,
    const float* __restrict__ bvec, const float* __restrict__ res,
    const float* __restrict__ w1,
    float* __restrict__ hs, __half* __restrict__ hn16)
{
    __shared__ float red[9];
    size_t base = (size_t)blockIdx.x * DMODEL;
    int t = threadIdx.x;
    float v0 = x[base+t], v1 = x[base+t+256], v2 = x[base+t+512];
    float mu = blk_sum(v0+v1+v2, red) * (1.f/DMODEL);
    __syncthreads();
    float d0 = v0-mu, d1 = v1-mu, d2 = v2-mu;
    float var = blk_sum(d0*d0 + d1*d1 + d2*d2, red) * (1.f/DMODEL);
    float inv = rsqrtf(var + 1e-5f);
    float o0 = d0*inv*w[t]     + bvec[t]     + res[base+t];
    float o1 = d1*inv*w[t+256] + bvec[t+256] + res[base+t+256];
    float o2 = d2*inv*w[t+512] + bvec[t+512] + res[base+t+512];
    hs[base+t    ] = o0;
    hs[base+t+256] = o1;
    hs[base+t+512] = o2;
    __syncthreads();
    float ms = blk_sum(o0*o0 + o1*o1 + o2*o2, red) * (1.f/DMODEL);
    float rinv = rsqrtf(ms + 1e-6f);
    hn16[base+t    ] = __float2half_rn(w1[t]    *o0*rinv);
    hn16[base+t+256] = __float2half_rn(w1[t+256]*o1*rinv);
    hn16[base+t+512] = __float2half_rn(w1[t+512]*o2*rinv);
}

__global__ __launch_bounds__(256) void rms_kernel(
    const float* __restrict__ x, const float* __restrict__ w, __half* __restrict__ out)
{
    __shared__ float red[9];
    size_t base = (size_t)blockIdx.x * DMODEL;
    int t = threadIdx.x;
    float v0 = x[base+t], v1 = x[base+t+256], v2 = x[base+t+512];
    float ms = blk_sum(v0*v0 + v1*v1 + v2*v2, red) * (1.f/DMODEL);
    float inv = rsqrtf(ms + 1e-6f);
    out[base+t    ] = __float2half_rn(w[t]    *v0*inv);
    out[base+t+256] = __float2half_rn(w[t+256]*v1*inv);
    out[base+t+512] = __float2half_rn(w[t+512]*v2*inv);
}

// ---------------- launch ----------------
extern "C" void kernel_launch(void* const* d_in, const int* in_sizes, int n_in,
                              void* d_out, int out_size)
{
    const float* hidden  = (const float*)d_in[0];
    const float* bbox    = (const float*)d_in[1];
    const float* fc1_w   = (const float*)d_in[2];
    const float* fc1_b   = (const float*)d_in[3];
    const float* conv_w  = (const float*)d_in[4];
    const float* conv_b  = (const float*)d_in[5];
    const float* fc2_w   = (const float*)d_in[6];
    const float* fc2_b   = (const float*)d_in[7];
    const float* ln_ad_w = (const float*)d_in[8];
    const float* ln_ad_b = (const float*)d_in[9];
    const float* ln1_w   = (const float*)d_in[10];
    const float* q_w     = (const float*)d_in[11];
    const float* k_w     = (const float*)d_in[12];
    const float* v_w     = (const float*)d_in[13];
    const float* o_w     = (const float*)d_in[14];
    const float* rel_b   = (const float*)d_in[15];
    const float* ln2_w   = (const float*)d_in[16];
    const float* wi_w    = (const float*)d_in[17];
    const float* wo_w    = (const float*)d_in[18];
    float* out = (float*)d_out;

    __half *h16, *h1h, *cv16, *hn16, *qkvh, *ctx16, *ff16, *attnh, *scoresh;
    __half *wtqkv, *wto, *wtwi, *wtwo, *wtf1, *wtf2;
    float *ad, *hs, *hs2;
    int* bkt;
    cudaGetSymbolAddress((void**)&h16,  g_h16);
    cudaGetSymbolAddress((void**)&h1h,  g_h1h);
    cudaGetSymbolAddress((void**)&cv16, g_cv16);
    cudaGetSymbolAddress((void**)&ad,   g_ad);
    cudaGetSymbolAddress((void**)&hs,   g_hs);
    cudaGetSymbolAddress((void**)&hn16, g_hn16);
    cudaGetSymbolAddress((void**)&qkvh, g_qkvh);
    cudaGetSymbolAddress((void**)&ctx16,g_ctx16);
    cudaGetSymbolAddress((void**)&hs2,  g_hs2);
    cudaGetSymbolAddress((void**)&scoresh, g_scoresh);
    cudaGetSymbolAddress((void**)&attnh,g_attnh);
    cudaGetSymbolAddress((void**)&ff16, g_ff16);
    cudaGetSymbolAddress((void**)&bkt,  g_bucket);
    cudaGetSymbolAddress((void**)&wtqkv,g_wt_qkv);
    cudaGetSymbolAddress((void**)&wto,  g_wt_o);
    cudaGetSymbolAddress((void**)&wtwi, g_wt_wi);
    cudaGetSymbolAddress((void**)&wtwo, g_wt_wo);
    cudaGetSymbolAddress((void**)&wtf1, g_wt_fc1);
    cudaGetSymbolAddress((void**)&wtf2, g_wt_fc2);

    cudaFuncSetAttribute(hgemm<4>, cudaFuncAttributeMaxDynamicSharedMemorySize, SMEMB);
    cudaFuncSetAttribute(hgemm_m64<1>, cudaFuncAttributeMaxDynamicSharedMemorySize, SMEMB64);
    cudaFuncSetAttribute(hgemm_m64<2>, cudaFuncAttributeMaxDynamicSharedMemorySize, SMEMB64);
    cudaFuncSetAttribute(hgemm_m64<3>, cudaFuncAttributeMaxDynamicSharedMemorySize, SMEMB64);
    cudaFuncSetAttribute(hgemm_m16, cudaFuncAttributeMaxDynamicSharedMemorySize, SMEMB16);
    cudaFuncSetAttribute(qk_gemm,  cudaFuncAttributeMaxDynamicSharedMemorySize, SMEMB);
    cudaFuncSetAttribute(av_gemm,  cudaFuncAttributeMaxDynamicSharedMemorySize, AVSMEM);
    cudaFuncSetAttribute(bbox_softmax2, cudaFuncAttributeMaxDynamicSharedMemorySize, BB2_SMEM);

    // build job table
    TJobs J;
    const float* srcs[NJOBS] = {fc1_w, fc2_w, q_w, k_w, v_w, o_w, wi_w, wo_w};
    __half* dsts[NJOBS] = {wtf1, wtf2, wtqkv, wtqkv + DMODEL*DMODEL,
                           wtqkv + 2*DMODEL*DMODEL, wto, wtwi, wtwo};
    int Rs[NJOBS] = {DMODEL, ADC, DMODEL, DMODEL, DMODEL, DMODEL, DMODEL, DFF};
    int Cs[NJOBS] = {ADC, DMODEL, DMODEL, DMODEL, DMODEL, DMODEL, DFF, DMODEL};
    int acc = 0;
    for (int j = 0; j < NJOBS; j++) {
        J.src[j] = srcs[j]; J.dst[j] = dsts[j];
        J.R[j] = Rs[j]; J.C[j] = Cs[j];
        J.start[j] = acc;
        acc += (Rs[j] >> 5) * (Cs[j] >> 5);
    }
    J.start[NJOBS] = acc;

    dim3 tb(32, 8);
    mega_transpose<<<acc, tb>>>(J);                                                   // 0
    prep_kernel<<<ROUND_BLOCKS + SEQ, 256>>>(hidden, h16, bkt);                       // 1
    hgemm_m16<<<dim3(1, 256), 256, SMEMB16>>>(h16, wtf1, h1h, ADC, DMODEL, fc1_b);    // 2
    conv_kernel<<<ROWS, ADC>>>(h1h, conv_w, conv_b, cv16);                            // 3
    hgemm_m64<1><<<dim3(6, 64), 256, SMEMB64>>>(cv16, wtf2, ad, DMODEL, ADC, fc2_b);  // 4
    ln_res_rms_kernel<<<ROWS, 256>>>(ad, ln_ad_w, ln_ad_b, hidden, ln1_w, hs, hn16);  // 5
    hgemm<4><<<dim3(QKVN/128, 32), 256, SMEMB>>>(hn16, wtqkv, qkvh, QKVN, DMODEL, nullptr);
    qk_gemm<<<dim3(2, 2, BATCH*NHEADS), 256, SMEMB>>>(qkvh, scoresh);
    bbox_softmax2<<<dim3(BATCH, SEQ/8), 256, BB2_SMEM>>>(qkvh, bbox, rel_b, bkt, scoresh, attnh);
    av_gemm<<<dim3(2, BATCH*NHEADS), 256, AVSMEM>>>(attnh, qkvh, ctx16);
    hgemm_m64<3><<<dim3(6, 64), 256, SMEMB64>>>(ctx16, wto, hs2, DMODEL, DMODEL, hs);
    rms_kernel<<<ROWS, 256>>>(hs2, ln2_w, hn16);
    hgemm_m64<2><<<dim3(24, 64), 256, SMEMB64>>>(hn16, wtwi, ff16, DFF, DMODEL, nullptr);
    hgemm_m64<3><<<dim3(6, 64), 256, SMEMB64>>>(ff16, wtwo, out, DMODEL, DFF, hs2);
}